// round 7
// baseline (speedup 1.0000x reference)
#include <cuda_runtime.h>
#include <stdint.h>

// out_flat[4p+k] = X_flat[40p+10k+9] / X_flat[40p+10k] - 2,  k=0..3
//
// R7 = persistent single wave + SOFTWARE PIPELINE (fixes R6's stall):
// prefetch next tile's 5 dense LDG.128 into registers BEFORE gathering
// the current tile from SMEM; commit regs->SMEM after the gather. Loads
// stay in flight across every gather/store phase (sustained MLP=5/warp),
// unlike R6 where the single-buffer reuse serialized each iteration.

static constexpr long long N_FLOATS = 64LL * 512 * 4000;        // 131,072,000
static constexpr int TILE_F4   = 160;                            // float4 per warp-tile (640 floats)
static constexpr int TILE_OUT  = 64;                             // outputs per warp-tile
static constexpr int WARPS_PER_BLK = 8;
static constexpr int THREADS   = WARPS_PER_BLK * 32;
static constexpr int BLKS_PER_SM = 6;                            // 42-reg budget
static constexpr int N_BLOCKS  = 148 * BLKS_PER_SM;              // 888 = one wave
static constexpr uint32_t N_TILES = (uint32_t)(N_FLOATS / (TILE_F4 * 4)); // 204,800
static constexpr uint32_t WARPS_TOTAL = (uint32_t)N_BLOCKS * WARPS_PER_BLK; // 7104

__global__ __launch_bounds__(THREADS, BLKS_PER_SM) void ts_return_kernel(
    const float4* __restrict__ X4, float* __restrict__ out)
{
    __shared__ float s[WARPS_PER_BLK][TILE_F4 * 4];   // 640 floats / warp

    const uint32_t w = threadIdx.x >> 5;
    const uint32_t l = threadIdx.x & 31;
    const uint32_t gwarp = blockIdx.x * WARPS_PER_BLK + w;

    float* __restrict__ sw  = s[w];
    float4* __restrict__ sv = (float4*)sw;

    uint32_t tile = gwarp;
    if (tile >= N_TILES) return;   // (never true here; defensive)

    // Prologue: load tile 0 and commit to SMEM.
    {
        const float4* __restrict__ p = X4 + (size_t)tile * TILE_F4;
        float4 v0 = p[l], v1 = p[32 + l], v2 = p[64 + l],
               v3 = p[96 + l], v4 = p[128 + l];
        sv[l] = v0; sv[32 + l] = v1; sv[64 + l] = v2;
        sv[96 + l] = v3; sv[128 + l] = v4;
        __syncwarp();
    }

    while (true) {
        const uint32_t next = tile + WARPS_TOTAL;
        const bool has_next = (next < N_TILES);

        // Prefetch next tile into registers (5 independent LDG.128 in
        // flight during the gather below).
        float4 n0, n1, n2, n3, n4;
        if (has_next) {
            const float4* __restrict__ p = X4 + (size_t)next * TILE_F4;
            n0 = p[l]; n1 = p[32 + l]; n2 = p[64 + l];
            n3 = p[96 + l]; n4 = p[128 + l];
        }

        // Gather current tile: output o (0..63) needs sw[10o], sw[10o+9].
        uint32_t i0 = 10u * l;          // o = l
        uint32_t i1 = i0 + 320u;        // o = l + 32
        float r0 = __fdividef(sw[i0 + 9], sw[i0]) - 2.0f;
        float r1 = __fdividef(sw[i1 + 9], sw[i1]) - 2.0f;

        float* __restrict__ d = out + (size_t)tile * TILE_OUT;
        d[l]      = r0;    // coalesced 128B
        d[32 + l] = r1;    // coalesced 128B

        if (!has_next) break;

        __syncwarp();                   // all lanes done reading SMEM
        sv[l] = n0; sv[32 + l] = n1; sv[64 + l] = n2;
        sv[96 + l] = n3; sv[128 + l] = n4;
        __syncwarp();                   // SMEM ready for next gather

        tile = next;
    }
}

extern "C" void kernel_launch(void* const* d_in, const int* in_sizes, int n_in,
                              void* d_out, int out_size)
{
    const float4* X4 = (const float4*)d_in[0];
    float* out = (float*)d_out;
    ts_return_kernel<<<N_BLOCKS, THREADS>>>(X4, out);
}

// round 8
// speedup vs baseline: 1.0543x; 1.0543x over previous
#include <cuda_runtime.h>
#include <stdint.h>

// out_flat[4p+k] = X_flat[40p+10k+9] / X_flat[40p+10k] - 2,  k=0..3
// (row stride 4000 = 100 periods of 40 -> flat processing is exact)
//
// R8 = R4 structure (the proven winner: dense memcpy-identical load
// stream, warp-local SMEM gather, no block barrier, non-persistent grid
// whose CTA churn provides chip-level load pipelining) with FINER CTA
// granularity: 128-thread blocks, 2x the independent CTA streams per SM,
// halved wave quantum. Persistent variants (R6/R7) proven worse.

static constexpr long long N_FLOATS = 64LL * 512 * 4000;        // 131,072,000
static constexpr int TILE_F4   = 160;                            // float4 per warp-tile (640 floats)
static constexpr int TILE_OUT  = 64;                             // outputs per warp-tile
static constexpr int WARPS_PER_BLK = 4;
static constexpr int THREADS   = WARPS_PER_BLK * 32;             // 128
static constexpr long long N_TILES = N_FLOATS / (TILE_F4 * 4);   // 204,800
static constexpr int N_BLOCKS = (int)(N_TILES / WARPS_PER_BLK);  // 51,200

__global__ __launch_bounds__(THREADS) void ts_return_kernel(
    const float4* __restrict__ X4, float* __restrict__ out)
{
    __shared__ float s[WARPS_PER_BLK][TILE_F4 * 4];   // 640 floats / warp

    const uint32_t w = threadIdx.x >> 5;
    const uint32_t l = threadIdx.x & 31;
    const uint32_t tile = blockIdx.x * WARPS_PER_BLK + w;

    const float4* __restrict__ p = X4 + (size_t)tile * TILE_F4;

    // 5 independent, fully coalesced 128B-per-warp loads (dense stream).
    float4 v0 = p[l];
    float4 v1 = p[32 + l];
    float4 v2 = p[64 + l];
    float4 v3 = p[96 + l];
    float4 v4 = p[128 + l];

    float4* __restrict__ sv = (float4*)s[w];
    sv[l]        = v0;
    sv[32 + l]   = v1;
    sv[64 + l]   = v2;
    sv[96 + l]   = v3;
    sv[128 + l]  = v4;
    __syncwarp();

    // Gather: output o (0..63) needs s[10o] and s[10o+9].
    const float* __restrict__ sw = s[w];
    uint32_t i0 = 10u * l;          // o = l
    uint32_t i1 = i0 + 320u;        // o = l + 32
    float r0 = __fdividef(sw[i0 + 9], sw[i0]) - 2.0f;
    float r1 = __fdividef(sw[i1 + 9], sw[i1]) - 2.0f;

    float* __restrict__ d = out + (size_t)tile * TILE_OUT;
    d[l]      = r0;    // coalesced 128B
    d[32 + l] = r1;    // coalesced 128B
}

extern "C" void kernel_launch(void* const* d_in, const int* in_sizes, int n_in,
                              void* d_out, int out_size)
{
    const float4* X4 = (const float4*)d_in[0];
    float* out = (float*)d_out;
    ts_return_kernel<<<N_BLOCKS, THREADS>>>(X4, out);
}

// round 9
// speedup vs baseline: 1.0551x; 1.0008x over previous
#include <cuda_runtime.h>
#include <stdint.h>

// out_flat[4p+k] = X_flat[40p+10k+9] / X_flat[40p+10k] - 2,  k=0..3
// (row stride 4000 = 100 periods of 40 -> flat processing is exact)
//
// R9 = R8 structure (proven: dense memcpy-identical load stream,
// warp-local SMEM gather, no block barrier, non-persistent churn) at the
// finest CTA granularity: 64-thread blocks, 32 CTAs/SM resident. The
// 256->128 step improved DRAM% (88.0->88.9) and dur; this probes whether
// the churn-granularity trend continues or has saturated.

static constexpr long long N_FLOATS = 64LL * 512 * 4000;        // 131,072,000
static constexpr int TILE_F4   = 160;                            // float4 per warp-tile (640 floats)
static constexpr int TILE_OUT  = 64;                             // outputs per warp-tile
static constexpr int WARPS_PER_BLK = 2;
static constexpr int THREADS   = WARPS_PER_BLK * 32;             // 64
static constexpr long long N_TILES = N_FLOATS / (TILE_F4 * 4);   // 204,800
static constexpr int N_BLOCKS = (int)(N_TILES / WARPS_PER_BLK);  // 102,400

__global__ __launch_bounds__(THREADS) void ts_return_kernel(
    const float4* __restrict__ X4, float* __restrict__ out)
{
    __shared__ float s[WARPS_PER_BLK][TILE_F4 * 4];   // 640 floats / warp

    const uint32_t w = threadIdx.x >> 5;
    const uint32_t l = threadIdx.x & 31;
    const uint32_t tile = blockIdx.x * WARPS_PER_BLK + w;

    const float4* __restrict__ p = X4 + (size_t)tile * TILE_F4;

    // 5 independent, fully coalesced 128B-per-warp loads (dense stream).
    float4 v0 = p[l];
    float4 v1 = p[32 + l];
    float4 v2 = p[64 + l];
    float4 v3 = p[96 + l];
    float4 v4 = p[128 + l];

    float4* __restrict__ sv = (float4*)s[w];
    sv[l]        = v0;
    sv[32 + l]   = v1;
    sv[64 + l]   = v2;
    sv[96 + l]   = v3;
    sv[128 + l]  = v4;
    __syncwarp();

    // Gather: output o (0..63) needs s[10o] and s[10o+9].
    const float* __restrict__ sw = s[w];
    uint32_t i0 = 10u * l;          // o = l
    uint32_t i1 = i0 + 320u;        // o = l + 32
    float r0 = __fdividef(sw[i0 + 9], sw[i0]) - 2.0f;
    float r1 = __fdividef(sw[i1 + 9], sw[i1]) - 2.0f;

    float* __restrict__ d = out + (size_t)tile * TILE_OUT;
    d[l]      = r0;    // coalesced 128B
    d[32 + l] = r1;    // coalesced 128B
}

extern "C" void kernel_launch(void* const* d_in, const int* in_sizes, int n_in,
                              void* d_out, int out_size)
{
    const float4* X4 = (const float4*)d_in[0];
    float* out = (float*)d_out;
    ts_return_kernel<<<N_BLOCKS, THREADS>>>(X4, out);
}

// round 10
// speedup vs baseline: 1.0575x; 1.0023x over previous
#include <cuda_runtime.h>
#include <stdint.h>

// FINAL (converged, R9 structure).
// out_flat[4p+k] = X_flat[40p+10k+9] / X_flat[40p+10k] - 2,  k=0..3
// (row stride 4000 = 100 periods of 40 -> flat processing is exact)
//
// Design (each element evidence-backed across R1-R9):
//  - dense, memcpy-identical LDG.128 load stream (every byte consumed;
//    sparse/strided alternatives inflated L1/L2 traffic or request count)
//  - warp-local SMEM gather, __syncwarp only (block barriers chopped the
//    DRAM request stream; register-shuffle gather needs dynamic reg select)
//  - non-persistent grid: CTA churn supplies chip-level load pipelining
//    (persistent + software-pipelined variants both regressed)
//  - 64-thread CTAs: churn-granularity optimum (256->128 helped, 128->64 flat)
// Achieves 7.04 TB/s = 88% of HBM spec; kernel time ~= traffic/achieved-BW.

static constexpr long long N_FLOATS = 64LL * 512 * 4000;        // 131,072,000
static constexpr int TILE_F4   = 160;                            // float4 per warp-tile (640 floats)
static constexpr int TILE_OUT  = 64;                             // outputs per warp-tile
static constexpr int WARPS_PER_BLK = 2;
static constexpr int THREADS   = WARPS_PER_BLK * 32;             // 64
static constexpr long long N_TILES = N_FLOATS / (TILE_F4 * 4);   // 204,800
static constexpr int N_BLOCKS = (int)(N_TILES / WARPS_PER_BLK);  // 102,400

__global__ __launch_bounds__(THREADS) void ts_return_kernel(
    const float4* __restrict__ X4, float* __restrict__ out)
{
    __shared__ float s[WARPS_PER_BLK][TILE_F4 * 4];   // 640 floats / warp

    const uint32_t w = threadIdx.x >> 5;
    const uint32_t l = threadIdx.x & 31;
    const uint32_t tile = blockIdx.x * WARPS_PER_BLK + w;

    const float4* __restrict__ p = X4 + (size_t)tile * TILE_F4;

    // 5 independent, fully coalesced 128B-per-warp loads (dense stream).
    float4 v0 = p[l];
    float4 v1 = p[32 + l];
    float4 v2 = p[64 + l];
    float4 v3 = p[96 + l];
    float4 v4 = p[128 + l];

    float4* __restrict__ sv = (float4*)s[w];
    sv[l]        = v0;
    sv[32 + l]   = v1;
    sv[64 + l]   = v2;
    sv[96 + l]   = v3;
    sv[128 + l]  = v4;
    __syncwarp();

    // Gather: output o (0..63) needs s[10o] and s[10o+9].
    const float* __restrict__ sw = s[w];
    uint32_t i0 = 10u * l;          // o = l
    uint32_t i1 = i0 + 320u;        // o = l + 32
    float r0 = __fdividef(sw[i0 + 9], sw[i0]) - 2.0f;
    float r1 = __fdividef(sw[i1 + 9], sw[i1]) - 2.0f;

    float* __restrict__ d = out + (size_t)tile * TILE_OUT;
    d[l]      = r0;    // coalesced 128B
    d[32 + l] = r1;    // coalesced 128B
}

extern "C" void kernel_launch(void* const* d_in, const int* in_sizes, int n_in,
                              void* d_out, int out_size)
{
    const float4* X4 = (const float4*)d_in[0];
    float* out = (float*)d_out;
    ts_return_kernel<<<N_BLOCKS, THREADS>>>(X4, out);
}